// round 1
// baseline (speedup 1.0000x reference)
#include <cuda_runtime.h>
#include <cstdint>

// Problem constants (B=2, S=2048 -> N=4096 tokens; IN=2048, OUT=4096; C=128, K=16, V=16)
#define N_TOK   4096
#define C_BOOKS 128
#define K_CENT  16
#define V_LEN   16
#define IN_DIM  2048
#define OUT_DIM 4096
#define ROWS    (C_BOOKS * K_CENT)     // 2048 LUT rows
#define TO      16                     // output columns per slice
#define NSLICE  (OUT_DIM / TO)         // 256 slices
#define SROW    20                     // smem LUT row stride in floats (pad 16 -> 20, 80B = 16B-aligned)
#define IDXW    33                     // smem idx row stride in u32 (pad 32 -> 33, bank-conflict-free)
#define TN      1024                   // tokens per gather block

// Scratch (allocation-free rule: device globals)
__device__ unsigned char g_idx[(size_t)N_TOK * C_BOOKS];                 // 512 KB
__device__ float g_lut[(size_t)NSLICE * ROWS * TO];                      // 33.5 MB, tiled [slice][row][16]

// ---------------------------------------------------------------------------
// Kernel A: nearest-centroid indices (Chebyshev / p=inf), bit-exact vs ref.
// Grid: N/32 blocks x 256 threads. lane = token, warp owns 16 codebooks.
// Centroid reads are warp-uniform -> broadcast via L1.
// ---------------------------------------------------------------------------
__global__ void __launch_bounds__(256) quant_idx_kernel(
    const float* __restrict__ x, const float* __restrict__ cents)
{
    int tid   = threadIdx.x;
    int lane  = tid & 31;
    int w     = tid >> 5;                       // 0..7
    int token = blockIdx.x * 32 + lane;
    const float* xrow = x + (size_t)token * IN_DIM;

    for (int c = w * 16; c < w * 16 + 16; ++c) {
        float xv[16];
        const float4* xp = (const float4*)(xrow + c * V_LEN);
#pragma unroll
        for (int q = 0; q < 4; ++q) {
            float4 t = xp[q];
            xv[q * 4 + 0] = t.x; xv[q * 4 + 1] = t.y;
            xv[q * 4 + 2] = t.z; xv[q * 4 + 3] = t.w;
        }
        const float4* cb = (const float4*)(cents + (size_t)c * (K_CENT * V_LEN));
        float best = 3.4028235e38f;
        int   bi   = 0;
#pragma unroll
        for (int k = 0; k < K_CENT; ++k) {
            float d = 0.0f;
#pragma unroll
            for (int q = 0; q < 4; ++q) {
                float4 t = __ldg(cb + k * 4 + q);
                d = fmaxf(d, fabsf(xv[q * 4 + 0] - t.x));
                d = fmaxf(d, fabsf(xv[q * 4 + 1] - t.y));
                d = fmaxf(d, fabsf(xv[q * 4 + 2] - t.z));
                d = fmaxf(d, fabsf(xv[q * 4 + 3] - t.w));
            }
            if (d < best) { best = d; bi = k; }   // strict < keeps first min (matches argmin)
        }
        g_idx[(size_t)token * C_BOOKS + c] = (unsigned char)bi;
    }
}

// ---------------------------------------------------------------------------
// Kernel B: LUT[c,k,o] = sum_v cents[c,k,v] * W[c*16+v, o], written pre-tiled
// as g_lut[o>>4][c*16+k][o&15] so gather blocks stage contiguous 128KB.
// Grid: (128 codebooks, 16 o-chunks of 256) x 256 threads.
// ---------------------------------------------------------------------------
__global__ void __launch_bounds__(256) lut_kernel(
    const float* __restrict__ wgt, const float* __restrict__ cents)
{
    __shared__ float sc[K_CENT * V_LEN];        // 256 floats for this codebook
    int c = blockIdx.x;
    int o = blockIdx.y * 256 + threadIdx.x;
    sc[threadIdx.x] = cents[(size_t)c * 256 + threadIdx.x];
    __syncthreads();

    float acc[K_CENT];
#pragma unroll
    for (int k = 0; k < K_CENT; ++k) acc[k] = 0.0f;
#pragma unroll
    for (int v = 0; v < V_LEN; ++v) {
        float wv = wgt[(size_t)(c * V_LEN + v) * OUT_DIM + o];
#pragma unroll
        for (int k = 0; k < K_CENT; ++k)
            acc[k] = fmaf(sc[k * V_LEN + v], wv, acc[k]);
    }
    int slice = o >> 4, oo = o & 15;
#pragma unroll
    for (int k = 0; k < K_CENT; ++k)
        g_lut[((size_t)slice * ROWS + c * K_CENT + k) * TO + oo] = acc[k];
}

// ---------------------------------------------------------------------------
// Kernel C: out[n, o] = bias[o] + sum_c LUT[c, idx[n,c], o]
// Grid: (256 slices, N/TN) x 256 threads. Per block: stage the 128KB LUT
// slice into SMEM (padded rows), then 16 passes of 64 tokens x 4 float4-quads.
// ---------------------------------------------------------------------------
__global__ void __launch_bounds__(256, 1) gather_kernel(
    const float* __restrict__ bias, float* __restrict__ out)
{
    extern __shared__ float smem[];
    float*    s_lut = smem;                                 // ROWS*SROW floats
    uint32_t* s_idx = (uint32_t*)(smem + ROWS * SROW);      // 64*IDXW u32

    int slice = blockIdx.x;
    int tblk  = blockIdx.y;
    int tid   = threadIdx.x;
    int oq    = tid & 3;        // which float4 of the 16-col slice
    int tok   = tid >> 2;       // 0..63 token-in-pass

    // Stage LUT slice: contiguous global -> padded smem rows
    const float4* gsrc = (const float4*)(g_lut + (size_t)slice * ROWS * TO);
    for (int i = tid; i < ROWS * TO / 4; i += 256) {
        float4 v = gsrc[i];
        int r = i >> 2, cp = (i & 3) * 4;
        *(float4*)(s_lut + r * SROW + cp) = v;
    }

    float4 bv = *(const float4*)(bias + slice * TO + oq * 4);

    for (int pass = 0; pass < TN / 64; ++pass) {
        __syncthreads();   // lut ready (pass 0) + prior pass done with s_idx
        // Stage 64 tokens' indices (64 x 128B), padded rows for bank spread
        const uint32_t* gi =
            (const uint32_t*)(g_idx + (size_t)(tblk * TN + pass * 64) * C_BOOKS);
        for (int i = tid; i < 64 * 32; i += 256)
            s_idx[(i >> 5) * IDXW + (i & 31)] = gi[i];
        __syncthreads();

        float4 acc = make_float4(0.f, 0.f, 0.f, 0.f);
        const uint32_t* my_idx = s_idx + tok * IDXW;
#pragma unroll 4
        for (int c4 = 0; c4 < 32; ++c4) {
            uint32_t packed = my_idx[c4];
#pragma unroll
            for (int j = 0; j < 4; ++j) {
                int c = c4 * 4 + j;
                int k = (packed >> (8 * j)) & 0xFF;
                const float4 v = *(const float4*)(s_lut + (c * K_CENT + k) * SROW + oq * 4);
                acc.x += v.x; acc.y += v.y; acc.z += v.z; acc.w += v.w;
            }
        }
        int token = tblk * TN + pass * 64 + tok;
        float4 res = make_float4(acc.x + bv.x, acc.y + bv.y, acc.z + bv.z, acc.w + bv.w);
        *(float4*)(out + (size_t)token * OUT_DIM + slice * TO + oq * 4) = res;
    }
}

// ---------------------------------------------------------------------------
extern "C" void kernel_launch(void* const* d_in, const int* in_sizes, int n_in,
                              void* d_out, int out_size)
{
    const float* x     = (const float*)d_in[0];
    const float* wgt   = (const float*)d_in[1];
    const float* cents = (const float*)d_in[2];
    const float* bias  = (const float*)d_in[3];
    float*       out   = (float*)d_out;

    constexpr size_t smem_bytes = (ROWS * SROW + 64 * IDXW) * sizeof(float); // 172,288 B
    cudaFuncSetAttribute(gather_kernel,
                         cudaFuncAttributeMaxDynamicSharedMemorySize,
                         (int)smem_bytes);

    quant_idx_kernel<<<N_TOK / 32, 256>>>(x, cents);
    lut_kernel<<<dim3(C_BOOKS, OUT_DIM / 256), 256>>>(wgt, cents);
    gather_kernel<<<dim3(NSLICE, N_TOK / TN), 256, smem_bytes>>>(bias, out);
}

// round 2
// speedup vs baseline: 1.2882x; 1.2882x over previous
#include <cuda_runtime.h>
#include <cstdint>

// Problem constants (B=2, S=2048 -> N=4096 tokens; IN=2048, OUT=4096; C=128, K=16, V=16)
#define N_TOK   4096
#define C_BOOKS 128
#define K_CENT  16
#define V_LEN   16
#define IN_DIM  2048
#define OUT_DIM 4096
#define ROWS    (C_BOOKS * K_CENT)     // 2048 LUT rows
#define TO      16                     // output columns per slice
#define NSLICE  (OUT_DIM / TO)         // 256 slices
#define SROW    20                     // smem LUT row stride (floats); consecutive rows -> 8 distinct phase slots
#define TOKB    512                    // tokens per gather block

// Scratch (allocation-free rule: device globals)
__device__ unsigned char g_idxT[(size_t)C_BOOKS * N_TOK];        // [c][token], 512 KB
__device__ float g_lut[(size_t)NSLICE * ROWS * TO];              // 33.5 MB, tiled [slice][row][16]

// ---------------------------------------------------------------------------
// Kernel A: nearest-centroid indices (Chebyshev), bit-exact vs reference.
// Grid (128 token-blocks, 4 book-groups) x 256 thr -> 512 blocks (occupancy fix).
// Centroids staged in smem (warp-uniform reads -> broadcast, no L1 pressure).
// Writes transposed g_idxT[c][token] for the gather kernel.
// ---------------------------------------------------------------------------
__global__ void __launch_bounds__(256) quant_idx_kernel(
    const float* __restrict__ x, const float* __restrict__ cents)
{
    __shared__ float sc[32 * 256];              // 32 codebooks x 256 floats = 32 KB
    int tid   = threadIdx.x;
    int lane  = tid & 31;
    int w     = tid >> 5;                       // 0..7
    int token = blockIdx.x * 32 + lane;
    int cbase = blockIdx.y * 32;

    for (int i = tid; i < 32 * 256; i += 256)
        sc[i] = cents[(size_t)cbase * 256 + i];
    __syncthreads();

    const float* xrow = x + (size_t)token * IN_DIM;

    for (int cl = w * 4; cl < w * 4 + 4; ++cl) {
        int c = cbase + cl;
        float xv[16];
        const float4* xp = (const float4*)(xrow + c * V_LEN);
#pragma unroll
        for (int q = 0; q < 4; ++q) {
            float4 t = xp[q];
            xv[q * 4 + 0] = t.x; xv[q * 4 + 1] = t.y;
            xv[q * 4 + 2] = t.z; xv[q * 4 + 3] = t.w;
        }
        const float4* cb = (const float4*)(sc + cl * 256);
        float best = 3.4028235e38f;
        int   bi   = 0;
#pragma unroll
        for (int k = 0; k < K_CENT; ++k) {
            float d = 0.0f;
#pragma unroll
            for (int q = 0; q < 4; ++q) {
                float4 t = cb[k * 4 + q];
                d = fmaxf(d, fabsf(xv[q * 4 + 0] - t.x));
                d = fmaxf(d, fabsf(xv[q * 4 + 1] - t.y));
                d = fmaxf(d, fabsf(xv[q * 4 + 2] - t.z));
                d = fmaxf(d, fabsf(xv[q * 4 + 3] - t.w));
            }
            if (d < best) { best = d; bi = k; }   // strict < == first min (matches argmin)
        }
        g_idxT[(size_t)c * N_TOK + token] = (unsigned char)bi;
    }
}

// ---------------------------------------------------------------------------
// Kernel B: LUT[c,k,o] = sum_v cents[c,k,v] * W[c*16+v, o], pre-tiled as
// g_lut[o>>4][c*16+k][o&15] so gather blocks stage contiguous 128KB.
// ---------------------------------------------------------------------------
__global__ void __launch_bounds__(256) lut_kernel(
    const float* __restrict__ wgt, const float* __restrict__ cents)
{
    __shared__ float sc[K_CENT * V_LEN];
    int c = blockIdx.x;
    int o = blockIdx.y * 256 + threadIdx.x;
    sc[threadIdx.x] = cents[(size_t)c * 256 + threadIdx.x];
    __syncthreads();

    float acc[K_CENT];
#pragma unroll
    for (int k = 0; k < K_CENT; ++k) acc[k] = 0.0f;
#pragma unroll
    for (int v = 0; v < V_LEN; ++v) {
        float wv = wgt[(size_t)(c * V_LEN + v) * OUT_DIM + o];
#pragma unroll
        for (int k = 0; k < K_CENT; ++k)
            acc[k] = fmaf(sc[k * V_LEN + v], wv, acc[k]);
    }
    int slice = o >> 4, oo = o & 15;
#pragma unroll
    for (int k = 0; k < K_CENT; ++k)
        g_lut[((size_t)slice * ROWS + c * K_CENT + k) * TO + oo] = acc[k];
}

// ---------------------------------------------------------------------------
// Kernel C: shuffle-gather. out[n,o] = bias[o] + sum_c LUT[c, idx[n,c], o].
// Per codebook PAIR: lane l holds LUT row (pair*32 + l) (16 floats, registers).
// Each lane accumulates 2 tokens x 16 cols; gather = __shfl_sync by idx byte.
// No crossbar conflicts possible on the gather path.
// Grid (256 slices, 8 token-groups of 512) x 256 threads, 1 block/SM.
// ---------------------------------------------------------------------------
#define GAT(acc) do { \
    acc[0]  += __shfl_sync(0xffffffffu, C0.x, s_); \
    acc[1]  += __shfl_sync(0xffffffffu, C0.y, s_); \
    acc[2]  += __shfl_sync(0xffffffffu, C0.z, s_); \
    acc[3]  += __shfl_sync(0xffffffffu, C0.w, s_); \
    acc[4]  += __shfl_sync(0xffffffffu, C1.x, s_); \
    acc[5]  += __shfl_sync(0xffffffffu, C1.y, s_); \
    acc[6]  += __shfl_sync(0xffffffffu, C1.z, s_); \
    acc[7]  += __shfl_sync(0xffffffffu, C1.w, s_); \
    acc[8]  += __shfl_sync(0xffffffffu, C2.x, s_); \
    acc[9]  += __shfl_sync(0xffffffffu, C2.y, s_); \
    acc[10] += __shfl_sync(0xffffffffu, C2.z, s_); \
    acc[11] += __shfl_sync(0xffffffffu, C2.w, s_); \
    acc[12] += __shfl_sync(0xffffffffu, C3.x, s_); \
    acc[13] += __shfl_sync(0xffffffffu, C3.y, s_); \
    acc[14] += __shfl_sync(0xffffffffu, C3.z, s_); \
    acc[15] += __shfl_sync(0xffffffffu, C3.w, s_); \
} while (0)

__global__ void __launch_bounds__(256, 1) gather_kernel(
    const float* __restrict__ bias, float* __restrict__ out)
{
    extern __shared__ float smem[];
    float*         s_lut = smem;                                   // 2048 x SROW floats
    unsigned char* s_idx = (unsigned char*)(smem + ROWS * SROW);   // [128][512] bytes

    int slice = blockIdx.x;
    int tid   = threadIdx.x;
    int w     = tid >> 5;
    int lane  = tid & 31;
    int tok0  = blockIdx.y * TOKB;

    // Stage LUT slice (contiguous global -> padded smem rows, conflict-free)
    const float4* gsrc = (const float4*)(g_lut + (size_t)slice * ROWS * TO);
    for (int i = tid; i < ROWS * TO / 4; i += 256) {
        float4 v = gsrc[i];
        *(float4*)(s_lut + (i >> 2) * SROW + (i & 3) * 4) = v;
    }
    // Stage idx: 128 rows of 512 bytes (transposed, broadcast-friendly reads)
    uint4* sidx4 = (uint4*)s_idx;
    for (int i = tid; i < C_BOOKS * TOKB / 16; i += 256) {
        int c = i >> 5, jj = i & 31;
        sidx4[i] = *(const uint4*)(g_idxT + (size_t)c * N_TOK + tok0 + jj * 16);
    }
    __syncthreads();

    int la = w * 64 + lane;          // local token A; token B = la + 32
    float accA[16], accB[16];
#pragma unroll
    for (int j = 0; j < 16; ++j) { accA[j] = 0.0f; accB[j] = 0.0f; }

    // Preload step 0: lane l holds LUT row (0*32 + l)
    const float4* rp = (const float4*)(s_lut + (size_t)lane * SROW);
    float4 C0 = rp[0], C1 = rp[1], C2 = rp[2], C3 = rp[3];
    int a0 = s_idx[0 * TOKB + la];
    int a1 = s_idx[1 * TOKB + la];
    int b0 = s_idx[0 * TOKB + la + 32];
    int b1 = s_idx[1 * TOKB + la + 32];

#pragma unroll 1
    for (int s = 0; s < 63; ++s) {
        // Prefetch next pair's rows + indices (hides LDS latency behind shuffles)
        const float4* np = (const float4*)(s_lut + ((size_t)(2 * s + 2) * 16 + lane) * SROW);
        float4 P0 = np[0], P1 = np[1], P2 = np[2], P3 = np[3];
        int na0 = s_idx[(2 * s + 2) * TOKB + la];
        int na1 = s_idx[(2 * s + 3) * TOKB + la];
        int nb0 = s_idx[(2 * s + 2) * TOKB + la + 32];
        int nb1 = s_idx[(2 * s + 3) * TOKB + la + 32];

        { int s_ = a0;      GAT(accA); }
        { int s_ = a1 + 16; GAT(accA); }
        { int s_ = b0;      GAT(accB); }
        { int s_ = b1 + 16; GAT(accB); }

        C0 = P0; C1 = P1; C2 = P2; C3 = P3;
        a0 = na0; a1 = na1; b0 = nb0; b1 = nb1;
    }
    // Final pair (s = 63)
    { int s_ = a0;      GAT(accA); }
    { int s_ = a1 + 16; GAT(accA); }
    { int s_ = b0;      GAT(accB); }
    { int s_ = b1 + 16; GAT(accB); }

    // Epilogue: add bias, store 16 cols for both tokens
    const float4* bp = (const float4*)(bias + slice * TO);
    int tA = tok0 + la, tB = tA + 32;
    float* outA = out + (size_t)tA * OUT_DIM + slice * TO;
    float* outB = out + (size_t)tB * OUT_DIM + slice * TO;
#pragma unroll
    for (int q = 0; q < 4; ++q) {
        float4 bv = bp[q];
        float4 va = make_float4(accA[q * 4 + 0] + bv.x, accA[q * 4 + 1] + bv.y,
                                accA[q * 4 + 2] + bv.z, accA[q * 4 + 3] + bv.w);
        float4 vb = make_float4(accB[q * 4 + 0] + bv.x, accB[q * 4 + 1] + bv.y,
                                accB[q * 4 + 2] + bv.z, accB[q * 4 + 3] + bv.w);
        *(float4*)(outA + q * 4) = va;
        *(float4*)(outB + q * 4) = vb;
    }
}

// ---------------------------------------------------------------------------
extern "C" void kernel_launch(void* const* d_in, const int* in_sizes, int n_in,
                              void* d_out, int out_size)
{
    const float* x     = (const float*)d_in[0];
    const float* wgt   = (const float*)d_in[1];
    const float* cents = (const float*)d_in[2];
    const float* bias  = (const float*)d_in[3];
    float*       out   = (float*)d_out;

    constexpr size_t smem_bytes = ROWS * SROW * sizeof(float) + C_BOOKS * TOKB; // 163840 + 65536 = 229376
    cudaFuncSetAttribute(gather_kernel,
                         cudaFuncAttributeMaxDynamicSharedMemorySize,
                         (int)smem_bytes);

    quant_idx_kernel<<<dim3(N_TOK / 32, 4), 256>>>(x, cents);
    lut_kernel<<<dim3(C_BOOKS, OUT_DIM / 256), 256>>>(wgt, cents);
    gather_kernel<<<dim3(NSLICE, N_TOK / TOKB), 256, smem_bytes>>>(bias, out);
}

// round 4
// speedup vs baseline: 2.6066x; 2.0234x over previous
#include <cuda_runtime.h>
#include <cuda_fp16.h>
#include <cstdint>

// Problem constants
#define N_TOK   4096
#define C_BOOKS 128
#define K_CENT  16
#define V_LEN   16
#define IN_DIM  2048
#define OUT_DIM 4096
#define KTOT    2048                   // 128 books * 16 centroids (one-hot K)

// Scratch (allocation-free rule: device globals)
__device__ unsigned char g_idxT[(size_t)C_BOOKS * N_TOK];   // [c][token]
__device__ __half g_Bt[(size_t)OUT_DIM * KTOT];             // [o][k] k-contiguous, 16 MB

// ---------------------------------------------------------------------------
__device__ __forceinline__ uint32_t smem_u32(const void* p) {
    uint32_t a;
    asm("{ .reg .u64 t; cvta.to.shared.u64 t, %1; cvt.u32.u64 %0, t; }" : "=r"(a) : "l"(p));
    return a;
}
// one-hot half2: t==0 -> (1,0), t==1 -> (0,1), else (0,0)
__device__ __forceinline__ uint32_t oh(uint32_t t) {
    return t == 0u ? 0x3C00u : (t == 1u ? 0x3C000000u : 0u);
}

// ---------------------------------------------------------------------------
// Kernel A: nearest-centroid indices (Chebyshev), exact vs reference argmin.
// Writes transposed g_idxT[c][token].
// ---------------------------------------------------------------------------
__global__ void __launch_bounds__(256) quant_idx_kernel(
    const float* __restrict__ x, const float* __restrict__ cents)
{
    __shared__ float sc[32 * 256];
    int tid = threadIdx.x, lane = tid & 31, w = tid >> 5;
    int token = blockIdx.x * 32 + lane;
    int cbase = blockIdx.y * 32;

    for (int i = tid; i < 32 * 256; i += 256)
        sc[i] = cents[(size_t)cbase * 256 + i];
    __syncthreads();

    const float* xrow = x + (size_t)token * IN_DIM;
    for (int cl = w * 4; cl < w * 4 + 4; ++cl) {
        int c = cbase + cl;
        float xv[16];
        const float4* xp = (const float4*)(xrow + c * V_LEN);
#pragma unroll
        for (int q = 0; q < 4; ++q) {
            float4 t = xp[q];
            xv[q*4+0] = t.x; xv[q*4+1] = t.y; xv[q*4+2] = t.z; xv[q*4+3] = t.w;
        }
        const float4* cb = (const float4*)(sc + cl * 256);
        float best = 3.4028235e38f; int bi = 0;
#pragma unroll
        for (int k = 0; k < K_CENT; ++k) {
            float d = 0.0f;
#pragma unroll
            for (int q = 0; q < 4; ++q) {
                float4 t = cb[k * 4 + q];
                d = fmaxf(d, fabsf(xv[q*4+0] - t.x));
                d = fmaxf(d, fabsf(xv[q*4+1] - t.y));
                d = fmaxf(d, fabsf(xv[q*4+2] - t.z));
                d = fmaxf(d, fabsf(xv[q*4+3] - t.w));
            }
            if (d < best) { best = d; bi = k; }   // strict < == first min (matches argmin)
        }
        g_idxT[(size_t)c * N_TOK + token] = (unsigned char)bi;
    }
}

// ---------------------------------------------------------------------------
// Kernel B: LUT -> fp16 B^T.  g_Bt[o][c*16+k] = fp16( sum_v cents[c,k,v] * W[c*16+v, o] )
// ---------------------------------------------------------------------------
__global__ void __launch_bounds__(256) build_B_kernel(
    const float* __restrict__ wgt, const float* __restrict__ cents)
{
    __shared__ float sc[K_CENT * V_LEN];
    int c = blockIdx.x;
    int o = blockIdx.y * 256 + threadIdx.x;
    sc[threadIdx.x] = cents[(size_t)c * 256 + threadIdx.x];
    __syncthreads();

    float acc[K_CENT];
#pragma unroll
    for (int k = 0; k < K_CENT; ++k) acc[k] = 0.0f;
#pragma unroll
    for (int v = 0; v < V_LEN; ++v) {
        float wv = wgt[(size_t)(c * V_LEN + v) * OUT_DIM + o];
#pragma unroll
        for (int k = 0; k < K_CENT; ++k)
            acc[k] = fmaf(sc[k * V_LEN + v], wv, acc[k]);
    }
    __half2 h[8];
#pragma unroll
    for (int j = 0; j < 8; ++j)
        h[j] = __floats2half2_rn(acc[2 * j], acc[2 * j + 1]);
    uint4* dst = (uint4*)(g_Bt + (size_t)o * KTOT + c * 16);
    dst[0] = *(uint4*)&h[0];
    dst[1] = *(uint4*)&h[4];
}

// ---------------------------------------------------------------------------
// Kernel C: one-hot GEMM via mma.sync m16n8k16 (HMMA), A synthesized from idx.
// CTA tile 128 tokens x 128 outputs, 8 warps (warp tile 32x64).
// B staged in 64-k chunks, 144B-padded rows (conflict-free ldmatrix),
// double-buffered cp.async pipeline.
// ---------------------------------------------------------------------------
#define SM_IDX  0
#define BSTG    (128 * 144)            // 18432 B per stage
#define SM_B    16384
#define SM_BIAS (SM_B + 2 * BSTG)      // 53248
#define SM_TOT  (SM_BIAS + 512)        // 53760

#define MMA(d, a0, a1, a2, a3, b0, b1) \
    asm volatile("mma.sync.aligned.m16n8k16.row.col.f32.f16.f16.f32 " \
        "{%0,%1,%2,%3}, {%4,%5,%6,%7}, {%8,%9}, {%0,%1,%2,%3};" \
        : "+f"((d)[0]), "+f"((d)[1]), "+f"((d)[2]), "+f"((d)[3]) \
        : "r"(a0), "r"(a1), "r"(a2), "r"(a3), "r"(b0), "r"(b1))

__global__ void __launch_bounds__(256, 1) onehot_hmma_kernel(
    const float* __restrict__ bias, float* __restrict__ out)
{
    extern __shared__ __align__(128) unsigned char smem[];
    const uint32_t sb = smem_u32(smem);
    const int tid = threadIdx.x, lane = tid & 31, w = tid >> 5;
    const int ms = w & 3, ns = w >> 2;
    const int m0 = blockIdx.y * 128, o0 = blockIdx.x * 128;

    // Stage idx (128 books x 128 tokens) + bias
    {
        uint4* si = (uint4*)(smem + SM_IDX);
        for (int i = tid; i < 1024; i += 256)
            si[i] = *(const uint4*)(g_idxT + ((size_t)(i >> 3) << 12) + m0 + (i & 7) * 16);
        float* sbias = (float*)(smem + SM_BIAS);
        if (tid < 128) sbias[tid] = bias[o0 + tid];
    }

    const __half* gB = g_Bt + (size_t)o0 * KTOT;

    // Prologue: stages 0, 1
#pragma unroll
    for (int s = 0; s < 2; ++s) {
        uint32_t dst = sb + SM_B + s * BSTG;
        const __half* src = gB + s * 64;
#pragma unroll
        for (int r = 0; r < 4; ++r) {
            int i = tid + r * 256, n = i >> 3, ch = i & 7;
            uint32_t d = dst + n * 144 + ch * 16;
            const void* g = src + (size_t)n * KTOT + ch * 8;
            asm volatile("cp.async.cg.shared.global [%0], [%1], 16;" :: "r"(d), "l"(g));
        }
        asm volatile("cp.async.commit_group;" ::: "memory");
    }

    float acc[2][8][4];
#pragma unroll
    for (int mf = 0; mf < 2; ++mf)
#pragma unroll
        for (int nf = 0; nf < 8; ++nf)
#pragma unroll
            for (int q = 0; q < 4; ++q) acc[mf][nf][q] = 0.0f;

    const uint32_t c0  = (uint32_t)((lane & 3) * 2);
    const uint32_t lmb = (uint32_t)((lane & 7) * 144 + (lane >> 3) * 16);
    const unsigned char* s_idx = smem + SM_IDX;
    const int rbase = ms * 32 + (lane >> 2);

    for (int s = 0; s < 32; ++s) {
        asm volatile("cp.async.wait_group 1;" ::: "memory");
        __syncthreads();
        uint32_t bufB = sb + SM_B + (s & 1) * BSTG;
#pragma unroll
        for (int cb = 0; cb < 4; ++cb) {
            int c = s * 4 + cb;
            const unsigned char* ip = s_idx + (c << 7) + rbase;
            uint32_t i0 = ip[0], i1 = ip[8], i2 = ip[16], i3 = ip[24];
            uint32_t t0 = i0 ^ c0, t1 = i1 ^ c0, t2 = i2 ^ c0, t3 = i3 ^ c0;
            uint32_t a00 = oh(t0),     a01 = oh(t1);
            uint32_t a02 = oh(t0 ^ 8), a03 = oh(t1 ^ 8);
            uint32_t a10 = oh(t2),     a11 = oh(t3);
            uint32_t a12 = oh(t2 ^ 8), a13 = oh(t3 ^ 8);
            uint32_t kb = bufB + (uint32_t)(cb * 32) + lmb + (uint32_t)(ns * 64 * 144);
#pragma unroll
            for (int nf = 0; nf < 8; ++nf) {
                uint32_t b0, b1;
                asm volatile("ldmatrix.sync.aligned.m8n8.x2.shared.b16 {%0,%1}, [%2];"
                             : "=r"(b0), "=r"(b1) : "r"(kb + (uint32_t)(nf * 8 * 144)));
                MMA(acc[0][nf], a00, a01, a02, a03, b0, b1);
                MMA(acc[1][nf], a10, a11, a12, a13, b0, b1);
            }
        }
        __syncthreads();
        if (s + 2 < 32) {
            uint32_t dst = sb + SM_B + (s & 1) * BSTG;
            const __half* src = gB + (s + 2) * 64;
#pragma unroll
            for (int r = 0; r < 4; ++r) {
                int i = tid + r * 256, n = i >> 3, ch = i & 7;
                uint32_t d = dst + n * 144 + ch * 16;
                const void* g = src + (size_t)n * KTOT + ch * 8;
                asm volatile("cp.async.cg.shared.global [%0], [%1], 16;" :: "r"(d), "l"(g));
            }
        }
        asm volatile("cp.async.commit_group;" ::: "memory");
    }

    // Epilogue: add bias, store
    const float* sbias = (const float*)(smem + SM_BIAS);
#pragma unroll
    for (int mf = 0; mf < 2; ++mf) {
        int row = m0 + ms * 32 + mf * 16 + (lane >> 2);
#pragma unroll
        for (int nf = 0; nf < 8; ++nf) {
            int colL = ns * 64 + nf * 8 + (int)c0;
            float2 bv = *(const float2*)(sbias + colL);
            float2 v0 = make_float2(acc[mf][nf][0] + bv.x, acc[mf][nf][1] + bv.y);
            float2 v1 = make_float2(acc[mf][nf][2] + bv.x, acc[mf][nf][3] + bv.y);
            *(float2*)(out + (size_t)row * OUT_DIM + o0 + colL) = v0;
            *(float2*)(out + (size_t)(row + 8) * OUT_DIM + o0 + colL) = v1;
        }
    }
}

// ---------------------------------------------------------------------------
extern "C" void kernel_launch(void* const* d_in, const int* in_sizes, int n_in,
                              void* d_out, int out_size)
{
    const float* x     = (const float*)d_in[0];
    const float* wgt   = (const float*)d_in[1];
    const float* cents = (const float*)d_in[2];
    const float* bias  = (const float*)d_in[3];
    float*       out   = (float*)d_out;

    cudaFuncSetAttribute(onehot_hmma_kernel,
                         cudaFuncAttributeMaxDynamicSharedMemorySize, SM_TOT);

    quant_idx_kernel<<<dim3(N_TOK / 32, 4), 256>>>(x, cents);
    build_B_kernel<<<dim3(C_BOOKS, OUT_DIM / 256), 256>>>(wgt, cents);
    onehot_hmma_kernel<<<dim3(OUT_DIM / 128, N_TOK / 128), 256, SM_TOT>>>(bias, out);
}